// round 12
// baseline (speedup 1.0000x reference)
#include <cuda_runtime.h>
#include <math.h>

#define NFRAMES 480          // B(16) * STEPS(30)
#define KDIM    5625         // 75*75 pooled cells
#define NNEUR   54
#define NPAD    64
#define STEPS   30
#define BATCH   16
#define FT      8            // frames per fused block
#define CROWS   5            // pooled rows per chunk
#define CCELLS  (CROWS * 75) // 375 cells per chunk
#define NCHUNK  15           // 75 / CROWS
#define SMEM_PAD 18432       // dynamic smem pad -> ~46.8KB/block -> 4 blocks/SM -> 2 waves

// -------- scratch (device globals; no allocation allowed) --------
__device__ float g_wT[KDIM * NPAD];                     // transposed padded weights ~1.44 MB
__device__ float g_partial[NCHUNK * NFRAMES * NNEUR];   // split-K partials
__device__ float g_frames[NFRAMES * NNEUR];             // merged FC outputs

// ================= 1) tiled transpose: fc_w[54][5625] -> wT[5625][64] (zero-pad) =======
__global__ void wT_kernel(const float* __restrict__ fc_w) {
    __shared__ float s[32 * 65];                // s[kk*65 + n], pad 65 -> conflict-free
    const int tid = threadIdx.x;
    const int k0  = blockIdx.x * 32;

    for (int idx = tid; idx < NNEUR * 32; idx += 256) {
        int n  = idx >> 5;
        int kk = idx & 31;
        float v = (k0 + kk < KDIM) ? fc_w[(size_t)n * KDIM + k0 + kk] : 0.f;
        s[kk * 65 + n] = v;
    }
    __syncthreads();

    const int n = tid & 63;
#pragma unroll
    for (int kk = tid >> 6; kk < 32; kk += 4) {
        if (k0 + kk < KDIM)
            g_wT[(size_t)(k0 + kk) * NPAD + n] = (n < NNEUR) ? s[kk * 65 + n] : 0.f;
    }
}

// ================= 2) fused pool(8x8 avg) + FC =========================================
// grid (60, 15), 256 threads, +SMEM_PAD dynamic smem to cap 4 blocks/SM (2 waves ->
// wave-2 pool overlaps wave-1 FC). FC: thread handles neurons (n, n+32), 8 k-groups,
// so each k-cell's 32B smem broadcast is read by exactly ONE warp (half the LDS ops).
__global__ void fused_kernel(const float* __restrict__ x) {
    __shared__ __align__(16) float xp_s[CCELLS * FT];  // 12000 B, [cell][frame]
    __shared__ float red[8 * FT * NPAD];               // 16384 B
    extern __shared__ float dyn_pad[];                 // occupancy throttle (untouched)

    const int tid = threadIdx.x;
    const int f0  = blockIdx.x * FT;
    const int pr0 = blockIdx.y * CROWS;
    const int k0  = blockIdx.y * CCELLS;       // global pooled-cell base

    // ---- stage 1: pooling (one big batch, high MLP, evict-first stream)
    for (int idx = tid; idx < FT * CCELLS; idx += 256) {
        int f  = idx / CCELLS;
        int c  = idx - f * CCELLS;
        int pr = c / 75;
        int pc = c - pr * 75;
        const float* p = x + ((size_t)(f0 + f) * 600 + (size_t)(pr0 + pr) * 8) * 600 + pc * 8;
        float s = 0.f;
#pragma unroll
        for (int r = 0; r < 8; r++) {
            float4 a = __ldcs((const float4*)(p + (size_t)r * 600));
            float4 b = __ldcs((const float4*)(p + (size_t)r * 600 + 4));
            s += ((a.x + a.y) + (a.z + a.w)) + ((b.x + b.y) + (b.z + b.w));
        }
        xp_s[c * FT + f] = s * (1.f / 64.f);
    }
    __syncthreads();

    // ---- stage 2: FC. n = tid&31 (+32 pair), k-group g = tid>>5 (8 groups)
    const int n = tid & 31;
    const int g = tid >> 5;
    float acc0[FT], acc1[FT];
#pragma unroll
    for (int f = 0; f < FT; f++) { acc0[f] = 0.f; acc1[f] = 0.f; }

    for (int p = g; p < CCELLS; p += 8) {
        const float* wrow = &g_wT[(size_t)(k0 + p) * NPAD];
        float wa = wrow[n];                                // 128B coalesced, L2
        float wb = wrow[n + 32];                           // 128B coalesced, L2
        float4 xa = *(const float4*)&xp_s[p * FT];         // LDS.128 broadcast (1 warp)
        float4 xb = *(const float4*)&xp_s[p * FT + 4];
        acc0[0] += xa.x * wa;  acc0[1] += xa.y * wa;
        acc0[2] += xa.z * wa;  acc0[3] += xa.w * wa;
        acc0[4] += xb.x * wa;  acc0[5] += xb.y * wa;
        acc0[6] += xb.z * wa;  acc0[7] += xb.w * wa;
        acc1[0] += xa.x * wb;  acc1[1] += xa.y * wb;
        acc1[2] += xa.z * wb;  acc1[3] += xa.w * wb;
        acc1[4] += xb.x * wb;  acc1[5] += xb.y * wb;
        acc1[6] += xb.z * wb;  acc1[7] += xb.w * wb;
    }
#pragma unroll
    for (int f = 0; f < FT; f++) {
        red[(g * FT + f) * NPAD + n]      = acc0[f];
        red[(g * FT + f) * NPAD + n + 32] = acc1[f];
    }
    __syncthreads();

    // ---- stage 3: fixed-order reduction over 8 k-groups, write split-K partial
    for (int idx = tid; idx < FT * NPAD; idx += 256) {
        int f  = idx >> 6;
        int nn = idx & 63;
        float s01 = red[(0 * FT + f) * NPAD + nn] + red[(1 * FT + f) * NPAD + nn];
        float s23 = red[(2 * FT + f) * NPAD + nn] + red[(3 * FT + f) * NPAD + nn];
        float s45 = red[(4 * FT + f) * NPAD + nn] + red[(5 * FT + f) * NPAD + nn];
        float s67 = red[(6 * FT + f) * NPAD + nn] + red[(7 * FT + f) * NPAD + nn];
        float s = (s01 + s23) + (s45 + s67);
        if (nn < NNEUR)
            g_partial[((size_t)blockIdx.y * NFRAMES + (f0 + f)) * NNEUR + nn] = s;
    }
    (void)dyn_pad;
}

// ================= 3) merge partials + bias, float4 (fixed order per component) ========
__global__ void merge_kernel(const float* __restrict__ fc_b) {
    int i4 = blockIdx.x * blockDim.x + threadIdx.x;     // float4 index
    if (i4 >= NFRAMES * NNEUR / 4) return;              // 6480
    int base = i4 * 4;
    float4 s;
    s.x = fc_b[(base + 0) % NNEUR];
    s.y = fc_b[(base + 1) % NNEUR];
    s.z = fc_b[(base + 2) % NNEUR];
    s.w = fc_b[(base + 3) % NNEUR];
#pragma unroll
    for (int c = 0; c < NCHUNK; c++) {
        float4 p = *(const float4*)&g_partial[(size_t)c * (NFRAMES * NNEUR) + base];
        s.x += p.x; s.y += p.y; s.z += p.z; s.w += p.w;
    }
    *(float4*)&g_frames[base] = s;
}

// ================= 4) spike scan (R7 structure — measured optimum, do not touch) =======
__global__ void __launch_bounds__(512) scan_kernel(
        const float* __restrict__ lw, const float* __restrict__ hw,
        float* __restrict__ out) {
    __shared__ __align__(16) float wr[2][16];

    const int tid  = threadIdx.x;            // 0..511
    const int b    = tid >> 5;               // batch == warp id
    const int lane = tid & 31;
    const bool actb = (lane < NNEUR - 32);   // slot B active: lane+32 < 54

    float fra[STEPS], frb[STEPS];
#pragma unroll
    for (int t = 0; t < STEPS; t++) {
        const float* row = g_frames + (b * STEPS + t) * NNEUR;
        fra[t] = row[lane];
        frb[t] = actb ? row[lane + 32] : 0.f;
    }

    const float w0 = hw[0], w1 = hw[1], w2 = hw[2], w3 = hw[3];
    const float la0 = lw[lane*4+0], la1 = lw[lane*4+1], la2 = lw[lane*4+2], la3 = lw[lane*4+3];
    float lb0 = 0.f, lb1 = 0.f, lb2 = 0.f, lb3 = 0.f;
    if (actb) { lb0 = lw[(lane+32)*4+0]; lb1 = lw[(lane+32)*4+1];
                lb2 = lw[(lane+32)*4+2]; lb3 = lw[(lane+32)*4+3]; }

    float a0=0.f,a1=0.f,a2=0.f,a3=0.f, b0=0.f,b1=0.f,b2=0.f,b3=0.f;
    float cnta = 0.f, cntb = 0.f;

#pragma unroll
    for (int t = 0; t < STEPS; t++) {
        float hsa = a0*la0 + a1*la1 + a2*la2 + a3*la3;
        float hsb = b0*lb0 + b1*lb1 + b2*lb2 + b3*lb3;   // 0 for inactive
        float hha = a0*w0 + a1*w1 + a2*w2 + a3*w3;
        float hhb = b0*w0 + b1*w1 + b2*w2 + b3*w3;

        float ea = expf(fra[t] - hsa + hha);             // no reduction dependency
        float eb = actb ? expf(frb[t] - hsb + hhb) : 0.f;

        float v = hsa + hsb;
        float s = ea + eb;
        v += __shfl_xor_sync(0xffffffffu, v, 16);  s += __shfl_xor_sync(0xffffffffu, s, 16);
        v += __shfl_xor_sync(0xffffffffu, v, 8);   s += __shfl_xor_sync(0xffffffffu, s, 8);
        v += __shfl_xor_sync(0xffffffffu, v, 4);   s += __shfl_xor_sync(0xffffffffu, s, 4);
        v += __shfl_xor_sync(0xffffffffu, v, 2);   s += __shfl_xor_sync(0xffffffffu, s, 2);
        v += __shfl_xor_sync(0xffffffffu, v, 1);   s += __shfl_xor_sync(0xffffffffu, s, 1);

        float ebb = expf(v);                             // exp(bsum), all lanes
        if (lane == 0) wr[t & 1][b] = ebb * s;           // batch rate sum
        __syncthreads();                                 // the only barrier per step

        const float4* w4 = (const float4*)wr[t & 1];
        float4 q0 = w4[0], q1 = w4[1], q2 = w4[2], q3 = w4[3];
        float tot = (((q0.x + q0.y) + (q0.z + q0.w)) + ((q1.x + q1.y) + (q1.z + q1.w)))
                  + (((q2.x + q2.y) + (q2.z + q2.w)) + ((q3.x + q3.y) + (q3.z + q3.w)));
        float thr = tot * (1.f / (BATCH * NNEUR));

        float sa = (ea * ebb > thr) ? 1.f : 0.f;
        float sb = (eb * ebb > thr) ? 1.f : 0.f;         // eb==0 -> never spikes (thr>0)
        cnta += sa;  cntb += sb;
        a0 = a1; a1 = a2; a2 = a3; a3 = sa;
        b0 = b1; b1 = b2; b2 = b3; b3 = sb;
    }
    out[b * NNEUR + lane] = cnta + log1pf(expf(-cnta));  // exact softplus, count>=0
    if (actb)
        out[b * NNEUR + lane + 32] = cntb + log1pf(expf(-cntb));
}

// =======================================================================================
extern "C" void kernel_launch(void* const* d_in, const int* in_sizes, int n_in,
                              void* d_out, int out_size) {
    const float* x    = (const float*)d_in[0];
    const float* fc_w = (const float*)d_in[1];
    const float* fc_b = (const float*)d_in[2];
    const float* lw   = (const float*)d_in[3];
    const float* hw   = (const float*)d_in[4];
    float* out = (float*)d_out;

    wT_kernel<<<(KDIM + 31) / 32, 256>>>(fc_w);
    fused_kernel<<<dim3(NFRAMES / FT, NCHUNK), 256, SMEM_PAD>>>(x);
    merge_kernel<<<(NFRAMES * NNEUR / 4 + 255) / 256, 256>>>(fc_b);
    scan_kernel<<<1, 512>>>(lw, hw, out);
    (void)in_sizes; (void)n_in; (void)out_size;
}

// round 14
// speedup vs baseline: 1.0020x; 1.0020x over previous
#include <cuda_runtime.h>
#include <math.h>

#define NFRAMES 480          // B(16) * STEPS(30)
#define KDIM    5625         // 75*75 pooled cells
#define NNEUR   54
#define NPAD    64
#define STEPS   30
#define BATCH   16
#define FT      8            // frames per fused block
#define CROWS   5            // pooled rows per chunk
#define CCELLS  (CROWS * 75) // 375 cells per chunk
#define NCHUNK  15           // 75 / CROWS

// -------- scratch (device globals; no allocation allowed) --------
__device__ float g_wT[KDIM * NPAD];                     // transposed padded weights ~1.44 MB
__device__ float g_partial[NCHUNK * NFRAMES * NNEUR];   // split-K partials
__device__ float g_frames[NFRAMES * NNEUR];             // merged FC outputs

// ================= 1) tiled transpose: fc_w[54][5625] -> wT[5625][64] (zero-pad) =======
__global__ void wT_kernel(const float* __restrict__ fc_w) {
    __shared__ float s[32 * 65];                // s[kk*65 + n], pad 65 -> conflict-free
    const int tid = threadIdx.x;
    const int k0  = blockIdx.x * 32;

    for (int idx = tid; idx < NNEUR * 32; idx += 256) {
        int n  = idx >> 5;
        int kk = idx & 31;
        float v = (k0 + kk < KDIM) ? fc_w[(size_t)n * KDIM + k0 + kk] : 0.f;
        s[kk * 65 + n] = v;
    }
    __syncthreads();

    const int n = tid & 63;
#pragma unroll
    for (int kk = tid >> 6; kk < 32; kk += 4) {
        if (k0 + kk < KDIM)
            g_wT[(size_t)(k0 + kk) * NPAD + n] = (n < NNEUR) ? s[kk * 65 + n] : 0.f;
    }
}

// ================= 2) fused pool(8x8 avg) + FC =========================================
// grid (60, 15), 256 threads, NO occupancy pad (8 blocks/SM, single wave — pool MLP is
// king). FC: thread handles neurons (n, n+32), 8 k-groups, so each k-cell's 32B smem
// broadcast is read by exactly ONE warp (half the LDS warp-ops of the 4-group version).
__global__ void fused_kernel(const float* __restrict__ x) {
    __shared__ __align__(16) float xp_s[CCELLS * FT];  // 12000 B, [cell][frame]
    __shared__ float red[8 * FT * NPAD];               // 16384 B

    const int tid = threadIdx.x;
    const int f0  = blockIdx.x * FT;
    const int pr0 = blockIdx.y * CROWS;
    const int k0  = blockIdx.y * CCELLS;       // global pooled-cell base

    // ---- stage 1: pooling (one big batch, high MLP, evict-first stream)
    for (int idx = tid; idx < FT * CCELLS; idx += 256) {
        int f  = idx / CCELLS;
        int c  = idx - f * CCELLS;
        int pr = c / 75;
        int pc = c - pr * 75;
        const float* p = x + ((size_t)(f0 + f) * 600 + (size_t)(pr0 + pr) * 8) * 600 + pc * 8;
        float s = 0.f;
#pragma unroll
        for (int r = 0; r < 8; r++) {
            float4 a = __ldcs((const float4*)(p + (size_t)r * 600));
            float4 b = __ldcs((const float4*)(p + (size_t)r * 600 + 4));
            s += ((a.x + a.y) + (a.z + a.w)) + ((b.x + b.y) + (b.z + b.w));
        }
        xp_s[c * FT + f] = s * (1.f / 64.f);
    }
    __syncthreads();

    // ---- stage 2: FC. n = tid&31 (+32 pair), k-group g = tid>>5 (8 groups)
    const int n = tid & 31;
    const int g = tid >> 5;
    float acc0[FT], acc1[FT];
#pragma unroll
    for (int f = 0; f < FT; f++) { acc0[f] = 0.f; acc1[f] = 0.f; }

    for (int p = g; p < CCELLS; p += 8) {
        const float* wrow = &g_wT[(size_t)(k0 + p) * NPAD];
        float wa = wrow[n];                                // 128B coalesced, L2
        float wb = wrow[n + 32];                           // 128B coalesced, L2
        float4 xa = *(const float4*)&xp_s[p * FT];         // LDS.128 broadcast (1 warp)
        float4 xb = *(const float4*)&xp_s[p * FT + 4];
        acc0[0] += xa.x * wa;  acc0[1] += xa.y * wa;
        acc0[2] += xa.z * wa;  acc0[3] += xa.w * wa;
        acc0[4] += xb.x * wa;  acc0[5] += xb.y * wa;
        acc0[6] += xb.z * wa;  acc0[7] += xb.w * wa;
        acc1[0] += xa.x * wb;  acc1[1] += xa.y * wb;
        acc1[2] += xa.z * wb;  acc1[3] += xa.w * wb;
        acc1[4] += xb.x * wb;  acc1[5] += xb.y * wb;
        acc1[6] += xb.z * wb;  acc1[7] += xb.w * wb;
    }
#pragma unroll
    for (int f = 0; f < FT; f++) {
        red[(g * FT + f) * NPAD + n]      = acc0[f];
        red[(g * FT + f) * NPAD + n + 32] = acc1[f];
    }
    __syncthreads();

    // ---- stage 3: fixed-order reduction over 8 k-groups, write split-K partial
    for (int idx = tid; idx < FT * NPAD; idx += 256) {
        int f  = idx >> 6;
        int nn = idx & 63;
        float s01 = red[(0 * FT + f) * NPAD + nn] + red[(1 * FT + f) * NPAD + nn];
        float s23 = red[(2 * FT + f) * NPAD + nn] + red[(3 * FT + f) * NPAD + nn];
        float s45 = red[(4 * FT + f) * NPAD + nn] + red[(5 * FT + f) * NPAD + nn];
        float s67 = red[(6 * FT + f) * NPAD + nn] + red[(7 * FT + f) * NPAD + nn];
        float s = (s01 + s23) + (s45 + s67);
        if (nn < NNEUR)
            g_partial[((size_t)blockIdx.y * NFRAMES + (f0 + f)) * NNEUR + nn] = s;
    }
}

// ================= 3) merge partials + bias, float4 (fixed order per component) ========
__global__ void merge_kernel(const float* __restrict__ fc_b) {
    int i4 = blockIdx.x * blockDim.x + threadIdx.x;     // float4 index
    if (i4 >= NFRAMES * NNEUR / 4) return;              // 6480
    int base = i4 * 4;
    float4 s;
    s.x = fc_b[(base + 0) % NNEUR];
    s.y = fc_b[(base + 1) % NNEUR];
    s.z = fc_b[(base + 2) % NNEUR];
    s.w = fc_b[(base + 3) % NNEUR];
#pragma unroll
    for (int c = 0; c < NCHUNK; c++) {
        float4 p = *(const float4*)&g_partial[(size_t)c * (NFRAMES * NNEUR) + base];
        s.x += p.x; s.y += p.y; s.z += p.z; s.w += p.w;
    }
    *(float4*)&g_frames[base] = s;
}

// ================= 4) spike scan (R7 structure — measured optimum, do not touch) =======
__global__ void __launch_bounds__(512) scan_kernel(
        const float* __restrict__ lw, const float* __restrict__ hw,
        float* __restrict__ out) {
    __shared__ __align__(16) float wr[2][16];

    const int tid  = threadIdx.x;            // 0..511
    const int b    = tid >> 5;               // batch == warp id
    const int lane = tid & 31;
    const bool actb = (lane < NNEUR - 32);   // slot B active: lane+32 < 54

    float fra[STEPS], frb[STEPS];
#pragma unroll
    for (int t = 0; t < STEPS; t++) {
        const float* row = g_frames + (b * STEPS + t) * NNEUR;
        fra[t] = row[lane];
        frb[t] = actb ? row[lane + 32] : 0.f;
    }

    const float w0 = hw[0], w1 = hw[1], w2 = hw[2], w3 = hw[3];
    const float la0 = lw[lane*4+0], la1 = lw[lane*4+1], la2 = lw[lane*4+2], la3 = lw[lane*4+3];
    float lb0 = 0.f, lb1 = 0.f, lb2 = 0.f, lb3 = 0.f;
    if (actb) { lb0 = lw[(lane+32)*4+0]; lb1 = lw[(lane+32)*4+1];
                lb2 = lw[(lane+32)*4+2]; lb3 = lw[(lane+32)*4+3]; }

    float a0=0.f,a1=0.f,a2=0.f,a3=0.f, b0=0.f,b1=0.f,b2=0.f,b3=0.f;
    float cnta = 0.f, cntb = 0.f;

#pragma unroll
    for (int t = 0; t < STEPS; t++) {
        float hsa = a0*la0 + a1*la1 + a2*la2 + a3*la3;
        float hsb = b0*lb0 + b1*lb1 + b2*lb2 + b3*lb3;   // 0 for inactive
        float hha = a0*w0 + a1*w1 + a2*w2 + a3*w3;
        float hhb = b0*w0 + b1*w1 + b2*w2 + b3*w3;

        float ea = expf(fra[t] - hsa + hha);             // no reduction dependency
        float eb = actb ? expf(frb[t] - hsb + hhb) : 0.f;

        float v = hsa + hsb;
        float s = ea + eb;
        v += __shfl_xor_sync(0xffffffffu, v, 16);  s += __shfl_xor_sync(0xffffffffu, s, 16);
        v += __shfl_xor_sync(0xffffffffu, v, 8);   s += __shfl_xor_sync(0xffffffffu, s, 8);
        v += __shfl_xor_sync(0xffffffffu, v, 4);   s += __shfl_xor_sync(0xffffffffu, s, 4);
        v += __shfl_xor_sync(0xffffffffu, v, 2);   s += __shfl_xor_sync(0xffffffffu, s, 2);
        v += __shfl_xor_sync(0xffffffffu, v, 1);   s += __shfl_xor_sync(0xffffffffu, s, 1);

        float ebb = expf(v);                             // exp(bsum), all lanes
        if (lane == 0) wr[t & 1][b] = ebb * s;           // batch rate sum
        __syncthreads();                                 // the only barrier per step

        const float4* w4 = (const float4*)wr[t & 1];
        float4 q0 = w4[0], q1 = w4[1], q2 = w4[2], q3 = w4[3];
        float tot = (((q0.x + q0.y) + (q0.z + q0.w)) + ((q1.x + q1.y) + (q1.z + q1.w)))
                  + (((q2.x + q2.y) + (q2.z + q2.w)) + ((q3.x + q3.y) + (q3.z + q3.w)));
        float thr = tot * (1.f / (BATCH * NNEUR));

        float sa = (ea * ebb > thr) ? 1.f : 0.f;
        float sb = (eb * ebb > thr) ? 1.f : 0.f;         // eb==0 -> never spikes (thr>0)
        cnta += sa;  cntb += sb;
        a0 = a1; a1 = a2; a2 = a3; a3 = sa;
        b0 = b1; b1 = b2; b2 = b3; b3 = sb;
    }
    out[b * NNEUR + lane] = cnta + log1pf(expf(-cnta));  // exact softplus, count>=0
    if (actb)
        out[b * NNEUR + lane + 32] = cntb + log1pf(expf(-cntb));
}

// =======================================================================================
extern "C" void kernel_launch(void* const* d_in, const int* in_sizes, int n_in,
                              void* d_out, int out_size) {
    const float* x    = (const float*)d_in[0];
    const float* fc_w = (const float*)d_in[1];
    const float* fc_b = (const float*)d_in[2];
    const float* lw   = (const float*)d_in[3];
    const float* hw   = (const float*)d_in[4];
    float* out = (float*)d_out;

    wT_kernel<<<(KDIM + 31) / 32, 256>>>(fc_w);
    fused_kernel<<<dim3(NFRAMES / FT, NCHUNK), 256>>>(x);
    merge_kernel<<<(NFRAMES * NNEUR / 4 + 255) / 256, 256>>>(fc_b);
    scan_kernel<<<1, 512>>>(lw, hw, out);
    (void)in_sizes; (void)n_in; (void)out_size;
}

// round 15
// speedup vs baseline: 1.1087x; 1.1066x over previous
#include <cuda_runtime.h>
#include <math.h>

#define NFRAMES 480          // B(16) * STEPS(30)
#define KDIM    5625         // 75*75 pooled cells
#define NNEUR   54
#define NPAD    64
#define STEPS   30
#define BATCH   16
#define FT      8            // frames per fused block
#define CROWS   5            // pooled rows per chunk
#define CCELLS  (CROWS * 75) // 375 cells per chunk
#define NCHUNK  15           // 75 / CROWS

// -------- scratch (device globals; no allocation allowed) --------
__device__ float g_wT[KDIM * NPAD];                     // transposed padded weights ~1.44 MB
__device__ float g_partial[NCHUNK * NFRAMES * NNEUR];   // split-K partials
__device__ float g_frames[NFRAMES * NNEUR];             // merged FC outputs

// ================= 1) tiled transpose: fc_w[54][5625] -> wT[5625][64] (zero-pad) =======
__global__ void wT_kernel(const float* __restrict__ fc_w) {
    __shared__ float s[32 * 65];                // s[kk*65 + n], pad 65 -> conflict-free
    const int tid = threadIdx.x;
    const int k0  = blockIdx.x * 32;

    for (int idx = tid; idx < NNEUR * 32; idx += 256) {
        int n  = idx >> 5;
        int kk = idx & 31;
        float v = (k0 + kk < KDIM) ? fc_w[(size_t)n * KDIM + k0 + kk] : 0.f;
        s[kk * 65 + n] = v;
    }
    __syncthreads();

    const int n = tid & 63;
#pragma unroll
    for (int kk = tid >> 6; kk < 32; kk += 4) {
        if (k0 + kk < KDIM)
            g_wT[(size_t)(k0 + kk) * NPAD + n] = (n < NNEUR) ? s[kk * 65 + n] : 0.f;
    }
}

// ================= 2) fused pool(8x8 avg) + FC — R7/R11 structure ======================
// grid (60, 15), 256 threads, 20.2 KB static smem -> 8 blocks/SM (pool MLP is king;
// measured: any smem growth past this loses ~13us). FC: 4 k-groups, n = tid&63,
// f-minor smem tile read as 2x LDS.128 broadcast.
__global__ void fused_kernel(const float* __restrict__ x) {
    __shared__ __align__(16) float xp_s[CCELLS * FT];  // 12000 B, [cell][frame]
    __shared__ float red[4 * FT * NPAD];               //  8192 B

    const int tid = threadIdx.x;
    const int f0  = blockIdx.x * FT;
    const int pr0 = blockIdx.y * CROWS;
    const int k0  = blockIdx.y * CCELLS;       // global pooled-cell base

    // ---- stage 1: pooling (one big batch, high MLP, evict-first stream)
    for (int idx = tid; idx < FT * CCELLS; idx += 256) {
        int f  = idx / CCELLS;
        int c  = idx - f * CCELLS;
        int pr = c / 75;
        int pc = c - pr * 75;
        const float* p = x + ((size_t)(f0 + f) * 600 + (size_t)(pr0 + pr) * 8) * 600 + pc * 8;
        float s = 0.f;
#pragma unroll
        for (int r = 0; r < 8; r++) {
            float4 a = __ldcs((const float4*)(p + (size_t)r * 600));
            float4 b = __ldcs((const float4*)(p + (size_t)r * 600 + 4));
            s += ((a.x + a.y) + (a.z + a.w)) + ((b.x + b.y) + (b.z + b.w));
        }
        xp_s[c * FT + f] = s * (1.f / 64.f);
    }
    __syncthreads();

    // ---- stage 2: FC. n = tid&63, k-group g = tid>>6 (4 groups over 375 cells)
    const int n = tid & 63;
    const int g = tid >> 6;
    float acc[FT];
#pragma unroll
    for (int f = 0; f < FT; f++) acc[f] = 0.f;

    for (int p = g; p < CCELLS; p += 4) {
        float w = g_wT[(size_t)(k0 + p) * NPAD + n];       // coalesced 128B, L2-resident
        float4 xa = *(const float4*)&xp_s[p * FT];         // LDS.128 broadcast
        float4 xb = *(const float4*)&xp_s[p * FT + 4];
        acc[0] += xa.x * w;  acc[1] += xa.y * w;
        acc[2] += xa.z * w;  acc[3] += xa.w * w;
        acc[4] += xb.x * w;  acc[5] += xb.y * w;
        acc[6] += xb.z * w;  acc[7] += xb.w * w;
    }
#pragma unroll
    for (int f = 0; f < FT; f++)
        red[(g * FT + f) * NPAD + n] = acc[f];
    __syncthreads();

    // ---- stage 3: fixed-order reduction over 4 k-groups, write split-K partial
    for (int idx = tid; idx < FT * NPAD; idx += 256) {
        int f  = idx >> 6;
        int nn = idx & 63;
        float s = ((red[(0 * FT + f) * NPAD + nn] + red[(1 * FT + f) * NPAD + nn])
                +  (red[(2 * FT + f) * NPAD + nn] + red[(3 * FT + f) * NPAD + nn]));
        if (nn < NNEUR)
            g_partial[((size_t)blockIdx.y * NFRAMES + (f0 + f)) * NNEUR + nn] = s;
    }
}

// ================= 3) merge partials + bias, float4 (fixed order per component) ========
__global__ void merge_kernel(const float* __restrict__ fc_b) {
    int i4 = blockIdx.x * blockDim.x + threadIdx.x;     // float4 index
    if (i4 >= NFRAMES * NNEUR / 4) return;              // 6480
    int base = i4 * 4;
    float4 s;
    s.x = fc_b[(base + 0) % NNEUR];
    s.y = fc_b[(base + 1) % NNEUR];
    s.z = fc_b[(base + 2) % NNEUR];
    s.w = fc_b[(base + 3) % NNEUR];
#pragma unroll
    for (int c = 0; c < NCHUNK; c++) {
        float4 p = *(const float4*)&g_partial[(size_t)c * (NFRAMES * NNEUR) + base];
        s.x += p.x; s.y += p.y; s.z += p.z; s.w += p.w;
    }
    *(float4*)&g_frames[base] = s;
}

// ================= 4) spike scan (R7 structure — measured optimum, do not touch) =======
__global__ void __launch_bounds__(512) scan_kernel(
        const float* __restrict__ lw, const float* __restrict__ hw,
        float* __restrict__ out) {
    __shared__ __align__(16) float wr[2][16];

    const int tid  = threadIdx.x;            // 0..511
    const int b    = tid >> 5;               // batch == warp id
    const int lane = tid & 31;
    const bool actb = (lane < NNEUR - 32);   // slot B active: lane+32 < 54

    float fra[STEPS], frb[STEPS];
#pragma unroll
    for (int t = 0; t < STEPS; t++) {
        const float* row = g_frames + (b * STEPS + t) * NNEUR;
        fra[t] = row[lane];
        frb[t] = actb ? row[lane + 32] : 0.f;
    }

    const float w0 = hw[0], w1 = hw[1], w2 = hw[2], w3 = hw[3];
    const float la0 = lw[lane*4+0], la1 = lw[lane*4+1], la2 = lw[lane*4+2], la3 = lw[lane*4+3];
    float lb0 = 0.f, lb1 = 0.f, lb2 = 0.f, lb3 = 0.f;
    if (actb) { lb0 = lw[(lane+32)*4+0]; lb1 = lw[(lane+32)*4+1];
                lb2 = lw[(lane+32)*4+2]; lb3 = lw[(lane+32)*4+3]; }

    float a0=0.f,a1=0.f,a2=0.f,a3=0.f, b0=0.f,b1=0.f,b2=0.f,b3=0.f;
    float cnta = 0.f, cntb = 0.f;

#pragma unroll
    for (int t = 0; t < STEPS; t++) {
        float hsa = a0*la0 + a1*la1 + a2*la2 + a3*la3;
        float hsb = b0*lb0 + b1*lb1 + b2*lb2 + b3*lb3;   // 0 for inactive
        float hha = a0*w0 + a1*w1 + a2*w2 + a3*w3;
        float hhb = b0*w0 + b1*w1 + b2*w2 + b3*w3;

        float ea = expf(fra[t] - hsa + hha);             // no reduction dependency
        float eb = actb ? expf(frb[t] - hsb + hhb) : 0.f;

        float v = hsa + hsb;
        float s = ea + eb;
        v += __shfl_xor_sync(0xffffffffu, v, 16);  s += __shfl_xor_sync(0xffffffffu, s, 16);
        v += __shfl_xor_sync(0xffffffffu, v, 8);   s += __shfl_xor_sync(0xffffffffu, s, 8);
        v += __shfl_xor_sync(0xffffffffu, v, 4);   s += __shfl_xor_sync(0xffffffffu, s, 4);
        v += __shfl_xor_sync(0xffffffffu, v, 2);   s += __shfl_xor_sync(0xffffffffu, s, 2);
        v += __shfl_xor_sync(0xffffffffu, v, 1);   s += __shfl_xor_sync(0xffffffffu, s, 1);

        float ebb = expf(v);                             // exp(bsum), all lanes
        if (lane == 0) wr[t & 1][b] = ebb * s;           // batch rate sum
        __syncthreads();                                 // the only barrier per step

        const float4* w4 = (const float4*)wr[t & 1];
        float4 q0 = w4[0], q1 = w4[1], q2 = w4[2], q3 = w4[3];
        float tot = (((q0.x + q0.y) + (q0.z + q0.w)) + ((q1.x + q1.y) + (q1.z + q1.w)))
                  + (((q2.x + q2.y) + (q2.z + q2.w)) + ((q3.x + q3.y) + (q3.z + q3.w)));
        float thr = tot * (1.f / (BATCH * NNEUR));

        float sa = (ea * ebb > thr) ? 1.f : 0.f;
        float sb = (eb * ebb > thr) ? 1.f : 0.f;         // eb==0 -> never spikes (thr>0)
        cnta += sa;  cntb += sb;
        a0 = a1; a1 = a2; a2 = a3; a3 = sa;
        b0 = b1; b1 = b2; b2 = b3; b3 = sb;
    }
    out[b * NNEUR + lane] = cnta + log1pf(expf(-cnta));  // exact softplus, count>=0
    if (actb)
        out[b * NNEUR + lane + 32] = cntb + log1pf(expf(-cntb));
}

// =======================================================================================
extern "C" void kernel_launch(void* const* d_in, const int* in_sizes, int n_in,
                              void* d_out, int out_size) {
    const float* x    = (const float*)d_in[0];
    const float* fc_w = (const float*)d_in[1];
    const float* fc_b = (const float*)d_in[2];
    const float* lw   = (const float*)d_in[3];
    const float* hw   = (const float*)d_in[4];
    float* out = (float*)d_out;

    wT_kernel<<<(KDIM + 31) / 32, 256>>>(fc_w);
    fused_kernel<<<dim3(NFRAMES / FT, NCHUNK), 256>>>(x);
    merge_kernel<<<(NFRAMES * NNEUR / 4 + 255) / 256, 256>>>(fc_b);
    scan_kernel<<<1, 512>>>(lw, hw, out);
    (void)in_sizes; (void)n_in; (void)out_size;
}